// round 9
// baseline (speedup 1.0000x reference)
#include <cuda_runtime.h>

typedef unsigned int       u32;
typedef unsigned long long u64;

static __device__ __forceinline__ u64 ffma2(u64 a, u64 b, u64 c){
    u64 d; asm("fma.rn.f32x2 %0, %1, %2, %3;" : "=l"(d) : "l"(a), "l"(b), "l"(c)); return d;
}
static __device__ __forceinline__ u64 fadd2(u64 a, u64 b){
    u64 d; asm("add.rn.f32x2 %0, %1, %2;" : "=l"(d) : "l"(a), "l"(b)); return d;
}
static __device__ __forceinline__ u64 pack2(float x){
    u64 r; asm("mov.b64 %0, {%1, %1};" : "=l"(r) : "f"(x)); return r;
}
static __device__ __forceinline__ u64 pack2b(float x, float y){
    u64 r; asm("mov.b64 %0, {%1, %2};" : "=l"(r) : "f"(x), "f"(y)); return r;
}
static __device__ __forceinline__ float2 unpack2(u64 v){
    float lo, hi; asm("mov.b64 {%0, %1}, %2;" : "=f"(lo), "=f"(hi) : "l"(v)); return make_float2(lo, hi);
}
static __device__ __forceinline__ u32 smaddr(const void* p){
    u32 a; asm("{ .reg .u64 t; cvta.to.shared.u64 t, %1; cvt.u32.u64 %0, t; }" : "=r"(a) : "l"(p)); return a;
}
static __device__ __forceinline__ void cp16(u32 dst, const void* src){
    asm volatile("cp.async.cg.shared.global [%0], [%1], 16;" :: "r"(dst), "l"(src));
}
#define CP_COMMIT() asm volatile("cp.async.commit_group;" ::: "memory")
#define CP_WAIT0()  asm volatile("cp.async.wait_group 0;" ::: "memory")

// ---------------- smem layout (float offsets) ----------------
#define SHR   0        // SOBS [36][132] / SH1 [64][132] / PF buffer  = 8448
#define WRG   8448     // W1 compact [36][64]=2304, then W2 [64][64]=4096 (overwrites)
#define XST   10752    // 16 batches * 144 floats = 2304
#define SB1   13056    // 64
#define SB2   13120    // 64
#define SWD   13184    // 64 float2 = 128
#define SCC   13312    // 2 (+2 pad)
#define SMEM_FLOATS 13316   // 53264 B -> 4 CTAs/SM

#define BPB   128
#define TILEB 128
#define LDA   132

// one k-step: 8 batches (4 f32x2) x 8 outputs per thread; acc[o*4+bp]
#define K_STEP(AP, WP, KK) do { \
    ulonglong2 A0 = *(const ulonglong2*)((AP) + (KK)*LDA); \
    ulonglong2 A1 = *(const ulonglong2*)((AP) + (KK)*LDA + 4); \
    float4 W0 = *(const float4*)((WP) + (KK)*64); \
    float4 W1v = *(const float4*)((WP) + (KK)*64 + 4); \
    u64 a0 = A0.x, a1 = A0.y, a2 = A1.x, a3 = A1.y; \
    u64 w; \
    w = pack2(W0.x); acc[0]  = ffma2(a0,w,acc[0]);  acc[1]  = ffma2(a1,w,acc[1]);  acc[2]  = ffma2(a2,w,acc[2]);  acc[3]  = ffma2(a3,w,acc[3]); \
    w = pack2(W0.y); acc[4]  = ffma2(a0,w,acc[4]);  acc[5]  = ffma2(a1,w,acc[5]);  acc[6]  = ffma2(a2,w,acc[6]);  acc[7]  = ffma2(a3,w,acc[7]); \
    w = pack2(W0.z); acc[8]  = ffma2(a0,w,acc[8]);  acc[9]  = ffma2(a1,w,acc[9]);  acc[10] = ffma2(a2,w,acc[10]); acc[11] = ffma2(a3,w,acc[11]); \
    w = pack2(W0.w); acc[12] = ffma2(a0,w,acc[12]); acc[13] = ffma2(a1,w,acc[13]); acc[14] = ffma2(a2,w,acc[14]); acc[15] = ffma2(a3,w,acc[15]); \
    w = pack2(W1v.x); acc[16] = ffma2(a0,w,acc[16]); acc[17] = ffma2(a1,w,acc[17]); acc[18] = ffma2(a2,w,acc[18]); acc[19] = ffma2(a3,w,acc[19]); \
    w = pack2(W1v.y); acc[20] = ffma2(a0,w,acc[20]); acc[21] = ffma2(a1,w,acc[21]); acc[22] = ffma2(a2,w,acc[22]); acc[23] = ffma2(a3,w,acc[23]); \
    w = pack2(W1v.z); acc[24] = ffma2(a0,w,acc[24]); acc[25] = ffma2(a1,w,acc[25]); acc[26] = ffma2(a2,w,acc[26]); acc[27] = ffma2(a3,w,acc[27]); \
    w = pack2(W1v.w); acc[28] = ffma2(a0,w,acc[28]); acc[29] = ffma2(a1,w,acc[29]); acc[30] = ffma2(a2,w,acc[30]); acc[31] = ffma2(a3,w,acc[31]); \
} while(0)

__global__ __launch_bounds__(BPB, 4) void maddpg_v9_kernel(
    const float* __restrict__ x,
    const float* __restrict__ W1, const float* __restrict__ b1,
    const float* __restrict__ W2, const float* __restrict__ b2,
    const float* __restrict__ W3, const float* __restrict__ b3,
    const int* __restrict__ idx,
    float* __restrict__ out, int B)
{
    extern __shared__ float sm[];
    __shared__ int sIdx[8];
    __shared__ int sActive[5];
    const int tid  = threadIdx.x;
    const int wid  = tid >> 5;
    const int lane = tid & 31;
    const int tx  = tid & 15;
    const int ty  = tid >> 4;
    const u32 smb = smaddr(sm);
    const int b0  = blockIdx.x * TILEB;
    const long nf4 = (long)B * 35;

    // division-free staging map: warp handles 4 batches of the 16-batch wave
    const int slb = 4*wid + (lane >> 3);   // local batch 0..15
    const int sq  = lane & 7;              // float4 lane within batch
    const u32 sdst_base = smb + (u32)((XST + slb*144) * 4);

    // ---- issue stage wave 0 ----
    {
        long gb = ((long)(b0 + slb)) * 35;
        #pragma unroll
        for (int j = 0; j < 5; j++){
            int f4 = sq + 8*j;
            if (f4 < 35){
                long gi = gb + f4;
                if (gi < nf4) cp16(sdst_base + (u32)(f4*16), (const float4*)x + gi);
            }
        }
        CP_COMMIT();
    }
    if (tid < 8)  sIdx[tid] = idx[tid];
    if (tid < 5)  sActive[tid] = 0;
    // W1 compacted to 36 rows (structurally-zero obs rows dropped)
    #pragma unroll
    for (int j = 0; j < 5; j++){
        int i = j*BPB + tid;
        if (i < 576){
            int ck = i >> 4, nq = i & 15;
            int o;
            if (ck < 5)       o = ck;
            else if (ck < 11) { int m = (ck-5) >> 1; o = 5 + 3*m + ((ck-5)&1); }
            else              o = 14 + (ck - 11);
            ((float4*)(sm + WRG))[i] = ((const float4*)W1)[o*16 + nq];
        }
    }
    if (tid < 16) ((float4*)(sm + SB1))[tid] = ((const float4*)b1)[tid];
    else if (tid < 32) ((float4*)(sm + SB2))[tid-16] = ((const float4*)b2)[tid-16];
    if (tid < 64){
        float a1 = W3[tid*5+1], a2 = W3[tid*5+2], a3 = W3[tid*5+3], a4 = W3[tid*5+4];
        ((float2*)(sm + SWD))[tid] = make_float2(a1 - a2, a3 - a4);
    }
    if (tid == 0) *(float2*)(sm + SCC) = make_float2(b3[1]-b3[2], b3[3]-b3[4]);

    // obs-build role map: warp-uniform, half-warp sub-roles
    const int half = lane >> 4;
    const int olb  = lane & 15;            // batch 0..15 within wave

    // ---- 8 staging waves of 16 batches ----
    #pragma unroll 1
    for (int w = 0; w < 8; w++){
        CP_WAIT0();
        __syncthreads();
        {
            const float* xb = sm + XST + olb*144;
            const float p0 = xb[0], p1 = xb[1];
            float* ob = sm + SHR + (w*16 + olb);   // column, stride LDA
            if (wid == 0){
                if (half == 0){
                    ob[0*LDA] = p0;    ob[1*LDA] = p1;    ob[2*LDA] = xb[2];
                    ob[3*LDA] = xb[3]; ob[4*LDA] = xb[4];
                } else {
                    const float* r = xb + (sIdx[7] + 10)*7;   // obstacle 4
                    float dx = r[0]-p0, dy = r[1]-p1;
                    bool in = (dx*dx + dy*dy) < 0.0225f;
                    if (in) sActive[4] = 1;
                    ob[31*LDA] = in ? dx   : 0.0f;
                    ob[32*LDA] = in ? dy   : 0.0f;
                    ob[33*LDA] = in ? r[2] : 0.0f;
                    ob[34*LDA] = in ? r[3] : 0.0f;
                    ob[35*LDA] = in ? r[4] : 0.0f;
                }
            } else if (wid == 1){
                if (half == 0){
                    #pragma unroll
                    for (int m = 0; m < 2; m++){
                        const float* r = xb + sIdx[m]*7;
                        ob[(5+2*m)*LDA] = (r[5] + r[0]) - p0;
                        ob[(6+2*m)*LDA] = (r[6] + r[1]) - p1;
                    }
                } else {
                    const float* r = xb + sIdx[2]*7;
                    ob[9*LDA]  = (r[5] + r[0]) - p0;
                    ob[10*LDA] = (r[6] + r[1]) - p1;
                }
            } else {
                int m = (wid - 2)*2 + half;                   // obstacles 0..3
                const float* r = xb + (sIdx[3+m] + 10)*7;
                float dx = r[0]-p0, dy = r[1]-p1;
                bool in = (dx*dx + dy*dy) < 0.0225f;
                if (in) sActive[m] = 1;
                int kb = 11 + 5*m;
                ob[(kb+0)*LDA] = in ? dx   : 0.0f;
                ob[(kb+1)*LDA] = in ? dy   : 0.0f;
                ob[(kb+2)*LDA] = in ? r[2] : 0.0f;
                ob[(kb+3)*LDA] = in ? r[3] : 0.0f;
                ob[(kb+4)*LDA] = in ? r[4] : 0.0f;
            }
        }
        __syncthreads();
        if (w < 7){
            long gb = ((long)(b0 + (w+1)*16 + slb)) * 35;
            #pragma unroll
            for (int j = 0; j < 5; j++){
                int f4 = sq + 8*j;
                if (f4 < 35){
                    long gi = gb + f4;
                    if (gi < nf4) cp16(sdst_base + (u32)(f4*16), (const float4*)x + gi);
                }
            }
            CP_COMMIT();
        }
    }

    int act0 = sActive[0], act1 = sActive[1], act2 = sActive[2],
        act3 = sActive[3], act4 = sActive[4];

    // ---- GEMM1: [128 x 36] * [36 x 64] ----
    u64 acc[32];
    #pragma unroll
    for (int i = 0; i < 32; i++) acc[i] = 0ull;
    {
        const float* ap = sm + SHR + 8*tx;
        const float* wp = sm + WRG + 8*ty;
        #pragma unroll
        for (int k = 0; k < 11; k++) K_STEP(ap, wp, k);
        if (act0){
            #pragma unroll
            for (int k = 11; k < 16; k++) K_STEP(ap, wp, k);
        }
        if (act1){
            #pragma unroll
            for (int k = 16; k < 21; k++) K_STEP(ap, wp, k);
        }
        if (act2){
            #pragma unroll
            for (int k = 21; k < 26; k++) K_STEP(ap, wp, k);
        }
        if (act3){
            #pragma unroll
            for (int k = 26; k < 31; k++) K_STEP(ap, wp, k);
        }
        if (act4){
            #pragma unroll
            for (int k = 31; k < 36; k++) K_STEP(ap, wp, k);
        }
    }
    __syncthreads();     // all W1 + SOBS reads complete

    // ---- issue W2 load over the W1/XST region ----
    #pragma unroll
    for (int j = 0; j < 8; j++)
        cp16(smb + (u32)((WRG + (j*BPB + tid)*4) * 4), (const float4*)W2 + j*BPB + tid);
    CP_COMMIT();

    // ---- epilogue 1: relu(acc + b1) -> SH1 rows ----
    #pragma unroll
    for (int o = 0; o < 8; o++){
        float bv = sm[SB1 + 8*ty + o];
        float2 f0 = unpack2(acc[o*4+0]);
        float2 f1 = unpack2(acc[o*4+1]);
        float2 f2 = unpack2(acc[o*4+2]);
        float2 f3 = unpack2(acc[o*4+3]);
        float4 lo, hi;
        lo.x = fmaxf(f0.x + bv, 0.0f); lo.y = fmaxf(f0.y + bv, 0.0f);
        lo.z = fmaxf(f1.x + bv, 0.0f); lo.w = fmaxf(f1.y + bv, 0.0f);
        hi.x = fmaxf(f2.x + bv, 0.0f); hi.y = fmaxf(f2.y + bv, 0.0f);
        hi.z = fmaxf(f3.x + bv, 0.0f); hi.w = fmaxf(f3.y + bv, 0.0f);
        *(float4*)(sm + SHR + (8*ty + o)*LDA + 8*tx)     = lo;
        *(float4*)(sm + SHR + (8*ty + o)*LDA + 8*tx + 4) = hi;
    }
    CP_WAIT0();
    __syncthreads();     // SH1 visible + W2 landed

    // ---- GEMM2: [128 x 64] * [64 x 64] ----
    #pragma unroll
    for (int i = 0; i < 32; i++) acc[i] = 0ull;
    {
        const float* ap = sm + SHR + 8*tx;
        const float* wp = sm + WRG + 8*ty;
        #pragma unroll 8
        for (int k = 0; k < 64; k++) K_STEP(ap, wp, k);
    }
    __syncthreads();     // SH1 reads done; SHR free for PF buffer

    // ---- register fold ----
    {
        u64 pfx[4], pfy[4];
        #pragma unroll
        for (int bp = 0; bp < 4; bp++){ pfx[bp] = 0ull; pfy[bp] = 0ull; }
        #pragma unroll
        for (int o = 0; o < 8; o++){
            float bv = sm[SB2 + 8*ty + o];
            float2 wdv = ((const float2*)(sm + SWD))[8*ty + o];
            u64 wx = pack2(wdv.x), wy = pack2(wdv.y);
            #pragma unroll
            for (int bp = 0; bp < 4; bp++){
                float2 f = unpack2(acc[o*4 + bp]);
                u64 rr = pack2b(fmaxf(f.x + bv, 0.0f), fmaxf(f.y + bv, 0.0f));
                pfx[bp] = ffma2(rr, wx, pfx[bp]);
                pfy[bp] = ffma2(rr, wy, pfy[bp]);
            }
        }
        ulonglong2* pf = (ulonglong2*)(sm + SHR);
        #pragma unroll
        for (int bp = 0; bp < 4; bp++){
            ulonglong2 v; v.x = pfx[bp]; v.y = pfy[bp];
            pf[ty*64 + 4*tx + bp] = v;
        }
    }
    __syncthreads();

    // ---- reduce over ty, scale, clip, store ----
    if (tid < 64){
        const ulonglong2* pf = (const ulonglong2*)(sm + SHR);
        float2 cc = *(const float2*)(sm + SCC);
        u64 ax = pack2(cc.x), ay = pack2(cc.y);
        #pragma unroll
        for (int t = 0; t < 8; t++){
            ulonglong2 v = pf[t*64 + tid];
            ax = fadd2(ax, v.x);
            ay = fadd2(ay, v.y);
        }
        float2 rx = unpack2(ax);
        float2 ry = unpack2(ay);
        float v0 = rx.x * 0.1f, v1 = ry.x * 0.1f;
        float v2 = rx.y * 0.1f, v3 = ry.y * 0.1f;
        if (fabsf(v0) > 1.0f) v0 = copysignf(2.0f, v0);
        if (fabsf(v1) > 1.0f) v1 = copysignf(2.0f, v1);
        if (fabsf(v2) > 1.0f) v2 = copysignf(2.0f, v2);
        if (fabsf(v3) > 1.0f) v3 = copysignf(2.0f, v3);
        int b = b0 + 2*tid;
        if (b < B){
            float4 o4; o4.x = v0; o4.y = v1; o4.z = v2; o4.w = v3;
            ((float4*)out)[(b0 >> 1) + tid] = o4;
        }
    }
}

extern "C" void kernel_launch(void* const* d_in, const int* in_sizes, int n_in,
                              void* d_out, int out_size)
{
    const float* x  = (const float*)d_in[0];
    const float* W1 = (const float*)d_in[1];
    const float* b1 = (const float*)d_in[2];
    const float* W2 = (const float*)d_in[3];
    const float* b2 = (const float*)d_in[4];
    const float* W3 = (const float*)d_in[5];
    const float* b3 = (const float*)d_in[6];
    const int*  idx = (const int*)d_in[7];

    const int B = in_sizes[0] / 140;
    const int blocks = (B + TILEB - 1) / TILEB;
    const size_t smem = SMEM_FLOATS * sizeof(float);

    cudaFuncSetAttribute(maddpg_v9_kernel,
                         cudaFuncAttributeMaxDynamicSharedMemorySize, (int)smem);

    maddpg_v9_kernel<<<blocks, BPB, smem>>>(x, W1, b1, W2, b2, W3, b3, idx,
                                            (float*)d_out, B);
}

// round 10
// speedup vs baseline: 1.1059x; 1.1059x over previous
#include <cuda_runtime.h>

typedef unsigned int       u32;
typedef unsigned long long u64;

static __device__ __forceinline__ u64 ffma2(u64 a, u64 b, u64 c){
    u64 d; asm("fma.rn.f32x2 %0, %1, %2, %3;" : "=l"(d) : "l"(a), "l"(b), "l"(c)); return d;
}
static __device__ __forceinline__ u64 fadd2(u64 a, u64 b){
    u64 d; asm("add.rn.f32x2 %0, %1, %2;" : "=l"(d) : "l"(a), "l"(b)); return d;
}
static __device__ __forceinline__ u64 pack2(float x){
    u64 r; asm("mov.b64 %0, {%1, %1};" : "=l"(r) : "f"(x)); return r;
}
static __device__ __forceinline__ u64 pack2b(float x, float y){
    u64 r; asm("mov.b64 %0, {%1, %2};" : "=l"(r) : "f"(x), "f"(y)); return r;
}
static __device__ __forceinline__ float2 unpack2(u64 v){
    float lo, hi; asm("mov.b64 {%0, %1}, %2;" : "=f"(lo), "=f"(hi) : "l"(v)); return make_float2(lo, hi);
}
static __device__ __forceinline__ u32 smaddr(const void* p){
    u32 a; asm("{ .reg .u64 t; cvta.to.shared.u64 t, %1; cvt.u32.u64 %0, t; }" : "=r"(a) : "l"(p)); return a;
}
static __device__ __forceinline__ void cp16(u32 dst, const void* src){
    asm volatile("cp.async.cg.shared.global [%0], [%1], 16;" :: "r"(dst), "l"(src));
}
#define CP_COMMIT() asm volatile("cp.async.commit_group;" ::: "memory")
#define CP_WAIT0()  asm volatile("cp.async.wait_group 0;" ::: "memory")

// ---------------- smem layout (float offsets) ----------------
#define SHR   0        // SOBS [36][132] / SH1 [64][132] / PF buffer  = 8448
#define WRG   8448     // W1 compact [36][64]=2304, then W2 [64][64]=4096 (overwrites)
#define XST   10752    // 16 batches * 144 floats = 2304
#define SB1   13056    // 64
#define SB2   13120    // 64
#define SWD   13184    // 64 float2 = 128
#define SCC   13312    // 2 (+2 pad)
#define SMEM_FLOATS 13316   // 53264 B -> 4 CTAs/SM

#define BPB   128
#define TILEB 128
#define LDA   132

// one k-step: 4 batches (1 LDS.128, conflict-free) x 16 outputs per thread.
// acc[2*o + h], o=0..15 outputs, h=0,1 batch-pairs.
#define K_STEP(AP, WP, KK) do { \
    ulonglong2 Av = *(const ulonglong2*)((AP) + (KK)*LDA); \
    float4 Wa = *(const float4*)((WP) + (KK)*64); \
    float4 Wb = *(const float4*)((WP) + (KK)*64 + 4); \
    float4 Wc = *(const float4*)((WP) + (KK)*64 + 8); \
    float4 Wd = *(const float4*)((WP) + (KK)*64 + 12); \
    u64 a0 = Av.x, a1 = Av.y; \
    u64 w; \
    w = pack2(Wa.x); acc[0]  = ffma2(a0,w,acc[0]);  acc[1]  = ffma2(a1,w,acc[1]); \
    w = pack2(Wa.y); acc[2]  = ffma2(a0,w,acc[2]);  acc[3]  = ffma2(a1,w,acc[3]); \
    w = pack2(Wa.z); acc[4]  = ffma2(a0,w,acc[4]);  acc[5]  = ffma2(a1,w,acc[5]); \
    w = pack2(Wa.w); acc[6]  = ffma2(a0,w,acc[6]);  acc[7]  = ffma2(a1,w,acc[7]); \
    w = pack2(Wb.x); acc[8]  = ffma2(a0,w,acc[8]);  acc[9]  = ffma2(a1,w,acc[9]); \
    w = pack2(Wb.y); acc[10] = ffma2(a0,w,acc[10]); acc[11] = ffma2(a1,w,acc[11]); \
    w = pack2(Wb.z); acc[12] = ffma2(a0,w,acc[12]); acc[13] = ffma2(a1,w,acc[13]); \
    w = pack2(Wb.w); acc[14] = ffma2(a0,w,acc[14]); acc[15] = ffma2(a1,w,acc[15]); \
    w = pack2(Wc.x); acc[16] = ffma2(a0,w,acc[16]); acc[17] = ffma2(a1,w,acc[17]); \
    w = pack2(Wc.y); acc[18] = ffma2(a0,w,acc[18]); acc[19] = ffma2(a1,w,acc[19]); \
    w = pack2(Wc.z); acc[20] = ffma2(a0,w,acc[20]); acc[21] = ffma2(a1,w,acc[21]); \
    w = pack2(Wc.w); acc[22] = ffma2(a0,w,acc[22]); acc[23] = ffma2(a1,w,acc[23]); \
    w = pack2(Wd.x); acc[24] = ffma2(a0,w,acc[24]); acc[25] = ffma2(a1,w,acc[25]); \
    w = pack2(Wd.y); acc[26] = ffma2(a0,w,acc[26]); acc[27] = ffma2(a1,w,acc[27]); \
    w = pack2(Wd.z); acc[28] = ffma2(a0,w,acc[28]); acc[29] = ffma2(a1,w,acc[29]); \
    w = pack2(Wd.w); acc[30] = ffma2(a0,w,acc[30]); acc[31] = ffma2(a1,w,acc[31]); \
} while(0)

__global__ __launch_bounds__(BPB, 4) void maddpg_v10_kernel(
    const float* __restrict__ x,
    const float* __restrict__ W1, const float* __restrict__ b1,
    const float* __restrict__ W2, const float* __restrict__ b2,
    const float* __restrict__ W3, const float* __restrict__ b3,
    const int* __restrict__ idx,
    float* __restrict__ out, int B)
{
    extern __shared__ float sm[];
    __shared__ int sIdx[8];
    __shared__ int sActive[5];
    const int tid  = threadIdx.x;
    const int wid  = tid >> 5;       // warp -> output group 16*wid
    const int lane = tid & 31;       // lane -> batches 4*lane..4*lane+3
    const u32 smb = smaddr(sm);
    const int b0  = blockIdx.x * TILEB;
    const long nf4 = (long)B * 35;

    // division-free staging map: warp handles 4 batches of the 16-batch wave
    const int slb = 4*wid + (lane >> 3);
    const int sq  = lane & 7;
    const u32 sdst_base = smb + (u32)((XST + slb*144) * 4);

    // ---- issue stage wave 0 ----
    {
        long gb = ((long)(b0 + slb)) * 35;
        #pragma unroll
        for (int j = 0; j < 5; j++){
            int f4 = sq + 8*j;
            if (f4 < 35){
                long gi = gb + f4;
                if (gi < nf4) cp16(sdst_base + (u32)(f4*16), (const float4*)x + gi);
            }
        }
        CP_COMMIT();
    }
    if (tid < 8)  sIdx[tid] = idx[tid];
    if (tid < 5)  sActive[tid] = 0;
    // W1 compacted to 36 rows (structurally-zero obs rows dropped)
    #pragma unroll
    for (int j = 0; j < 5; j++){
        int i = j*BPB + tid;
        if (i < 576){
            int ck = i >> 4, nq = i & 15;
            int o;
            if (ck < 5)       o = ck;
            else if (ck < 11) { int m = (ck-5) >> 1; o = 5 + 3*m + ((ck-5)&1); }
            else              o = 14 + (ck - 11);
            ((float4*)(sm + WRG))[i] = ((const float4*)W1)[o*16 + nq];
        }
    }
    if (tid < 16) ((float4*)(sm + SB1))[tid] = ((const float4*)b1)[tid];
    else if (tid < 32) ((float4*)(sm + SB2))[tid-16] = ((const float4*)b2)[tid-16];
    if (tid < 64){
        float a1 = W3[tid*5+1], a2 = W3[tid*5+2], a3 = W3[tid*5+3], a4 = W3[tid*5+4];
        ((float2*)(sm + SWD))[tid] = make_float2(a1 - a2, a3 - a4);
    }
    if (tid == 0) *(float2*)(sm + SCC) = make_float2(b3[1]-b3[2], b3[3]-b3[4]);

    // obs-build role map: warp-uniform, half-warp sub-roles
    const int half = lane >> 4;
    const int olb  = lane & 15;

    // ---- 8 staging waves of 16 batches ----
    #pragma unroll 1
    for (int w = 0; w < 8; w++){
        CP_WAIT0();
        __syncthreads();
        {
            const float* xb = sm + XST + olb*144;
            const float p0 = xb[0], p1 = xb[1];
            float* ob = sm + SHR + (w*16 + olb);
            if (wid == 0){
                if (half == 0){
                    ob[0*LDA] = p0;    ob[1*LDA] = p1;    ob[2*LDA] = xb[2];
                    ob[3*LDA] = xb[3]; ob[4*LDA] = xb[4];
                } else {
                    const float* r = xb + (sIdx[7] + 10)*7;   // obstacle 4
                    float dx = r[0]-p0, dy = r[1]-p1;
                    bool in = (dx*dx + dy*dy) < 0.0225f;
                    if (in) sActive[4] = 1;
                    ob[31*LDA] = in ? dx   : 0.0f;
                    ob[32*LDA] = in ? dy   : 0.0f;
                    ob[33*LDA] = in ? r[2] : 0.0f;
                    ob[34*LDA] = in ? r[3] : 0.0f;
                    ob[35*LDA] = in ? r[4] : 0.0f;
                }
            } else if (wid == 1){
                if (half == 0){
                    #pragma unroll
                    for (int m = 0; m < 2; m++){
                        const float* r = xb + sIdx[m]*7;
                        ob[(5+2*m)*LDA] = (r[5] + r[0]) - p0;
                        ob[(6+2*m)*LDA] = (r[6] + r[1]) - p1;
                    }
                } else {
                    const float* r = xb + sIdx[2]*7;
                    ob[9*LDA]  = (r[5] + r[0]) - p0;
                    ob[10*LDA] = (r[6] + r[1]) - p1;
                }
            } else {
                int m = (wid - 2)*2 + half;                   // obstacles 0..3
                const float* r = xb + (sIdx[3+m] + 10)*7;
                float dx = r[0]-p0, dy = r[1]-p1;
                bool in = (dx*dx + dy*dy) < 0.0225f;
                if (in) sActive[m] = 1;
                int kb = 11 + 5*m;
                ob[(kb+0)*LDA] = in ? dx   : 0.0f;
                ob[(kb+1)*LDA] = in ? dy   : 0.0f;
                ob[(kb+2)*LDA] = in ? r[2] : 0.0f;
                ob[(kb+3)*LDA] = in ? r[3] : 0.0f;
                ob[(kb+4)*LDA] = in ? r[4] : 0.0f;
            }
        }
        __syncthreads();
        if (w < 7){
            long gb = ((long)(b0 + (w+1)*16 + slb)) * 35;
            #pragma unroll
            for (int j = 0; j < 5; j++){
                int f4 = sq + 8*j;
                if (f4 < 35){
                    long gi = gb + f4;
                    if (gi < nf4) cp16(sdst_base + (u32)(f4*16), (const float4*)x + gi);
                }
            }
            CP_COMMIT();
        }
    }

    int act0 = sActive[0], act1 = sActive[1], act2 = sActive[2],
        act3 = sActive[3], act4 = sActive[4];

    // ---- GEMM1: [128 x 36] * [36 x 64] ----
    u64 acc[32];
    #pragma unroll
    for (int i = 0; i < 32; i++) acc[i] = 0ull;
    {
        const float* ap = sm + SHR + 4*lane;
        const float* wp = sm + WRG + 16*wid;
        #pragma unroll
        for (int k = 0; k < 11; k++) K_STEP(ap, wp, k);
        if (act0){
            #pragma unroll
            for (int k = 11; k < 16; k++) K_STEP(ap, wp, k);
        }
        if (act1){
            #pragma unroll
            for (int k = 16; k < 21; k++) K_STEP(ap, wp, k);
        }
        if (act2){
            #pragma unroll
            for (int k = 21; k < 26; k++) K_STEP(ap, wp, k);
        }
        if (act3){
            #pragma unroll
            for (int k = 26; k < 31; k++) K_STEP(ap, wp, k);
        }
        if (act4){
            #pragma unroll
            for (int k = 31; k < 36; k++) K_STEP(ap, wp, k);
        }
    }
    __syncthreads();     // all W1 + SOBS reads complete

    // ---- issue W2 load over the W1/XST region ----
    #pragma unroll
    for (int j = 0; j < 8; j++)
        cp16(smb + (u32)((WRG + (j*BPB + tid)*4) * 4), (const float4*)W2 + j*BPB + tid);
    CP_COMMIT();

    // ---- epilogue 1: relu(acc + b1) -> SH1 rows (one contiguous STS.128 per output) ----
    #pragma unroll
    for (int o = 0; o < 16; o++){
        float bv = sm[SB1 + 16*wid + o];
        float2 f0 = unpack2(acc[2*o]);
        float2 f1 = unpack2(acc[2*o+1]);
        float4 v;
        v.x = fmaxf(f0.x + bv, 0.0f); v.y = fmaxf(f0.y + bv, 0.0f);
        v.z = fmaxf(f1.x + bv, 0.0f); v.w = fmaxf(f1.y + bv, 0.0f);
        *(float4*)(sm + SHR + (16*wid + o)*LDA + 4*lane) = v;
    }
    CP_WAIT0();
    __syncthreads();     // SH1 visible + W2 landed

    // ---- GEMM2: [128 x 64] * [64 x 64] ----
    #pragma unroll
    for (int i = 0; i < 32; i++) acc[i] = 0ull;
    {
        const float* ap = sm + SHR + 4*lane;
        const float* wp = sm + WRG + 16*wid;
        #pragma unroll 8
        for (int k = 0; k < 64; k++) K_STEP(ap, wp, k);
    }
    __syncthreads();     // SH1 reads done; SHR free for PF buffer

    // ---- register fold over this thread's 16 outputs ----
    {
        u64 pfx[2], pfy[2];
        pfx[0] = pfx[1] = pfy[0] = pfy[1] = 0ull;
        #pragma unroll
        for (int o = 0; o < 16; o++){
            float bv = sm[SB2 + 16*wid + o];
            float2 wdv = ((const float2*)(sm + SWD))[16*wid + o];
            u64 wx = pack2(wdv.x), wy = pack2(wdv.y);
            #pragma unroll
            for (int h = 0; h < 2; h++){
                float2 f = unpack2(acc[2*o + h]);
                u64 rr = pack2b(fmaxf(f.x + bv, 0.0f), fmaxf(f.y + bv, 0.0f));
                pfx[h] = ffma2(rr, wx, pfx[h]);
                pfy[h] = ffma2(rr, wy, pfy[h]);
            }
        }
        ulonglong2* pf = (ulonglong2*)(sm + SHR);
        #pragma unroll
        for (int h = 0; h < 2; h++){
            ulonglong2 v; v.x = pfx[h]; v.y = pfy[h];
            pf[wid*64 + 2*lane + h] = v;
        }
    }
    __syncthreads();

    // ---- reduce over 4 warps, scale, clip, store ----
    if (tid < 64){
        const ulonglong2* pf = (const ulonglong2*)(sm + SHR);
        float2 cc = *(const float2*)(sm + SCC);
        u64 ax = pack2(cc.x), ay = pack2(cc.y);
        #pragma unroll
        for (int t = 0; t < 4; t++){
            ulonglong2 v = pf[t*64 + tid];
            ax = fadd2(ax, v.x);
            ay = fadd2(ay, v.y);
        }
        float2 rx = unpack2(ax);
        float2 ry = unpack2(ay);
        float v0 = rx.x * 0.1f, v1 = ry.x * 0.1f;
        float v2 = rx.y * 0.1f, v3 = ry.y * 0.1f;
        if (fabsf(v0) > 1.0f) v0 = copysignf(2.0f, v0);
        if (fabsf(v1) > 1.0f) v1 = copysignf(2.0f, v1);
        if (fabsf(v2) > 1.0f) v2 = copysignf(2.0f, v2);
        if (fabsf(v3) > 1.0f) v3 = copysignf(2.0f, v3);
        int b = b0 + 2*tid;
        if (b < B){
            float4 o4; o4.x = v0; o4.y = v1; o4.z = v2; o4.w = v3;
            ((float4*)out)[(b0 >> 1) + tid] = o4;
        }
    }
}

extern "C" void kernel_launch(void* const* d_in, const int* in_sizes, int n_in,
                              void* d_out, int out_size)
{
    const float* x  = (const float*)d_in[0];
    const float* W1 = (const float*)d_in[1];
    const float* b1 = (const float*)d_in[2];
    const float* W2 = (const float*)d_in[3];
    const float* b2 = (const float*)d_in[4];
    const float* W3 = (const float*)d_in[5];
    const float* b3 = (const float*)d_in[6];
    const int*  idx = (const int*)d_in[7];

    const int B = in_sizes[0] / 140;
    const int blocks = (B + TILEB - 1) / TILEB;
    const size_t smem = SMEM_FLOATS * sizeof(float);

    cudaFuncSetAttribute(maddpg_v10_kernel,
                         cudaFuncAttributeMaxDynamicSharedMemorySize, (int)smem);

    maddpg_v10_kernel<<<blocks, BPB, smem>>>(x, W1, b1, W2, b2, W3, b3, idx,
                                             (float*)d_out, B);
}

// round 11
// speedup vs baseline: 1.1072x; 1.0013x over previous
#include <cuda_runtime.h>

typedef unsigned int       u32;
typedef unsigned long long u64;

static __device__ __forceinline__ u64 ffma2(u64 a, u64 b, u64 c){
    u64 d; asm("fma.rn.f32x2 %0, %1, %2, %3;" : "=l"(d) : "l"(a), "l"(b), "l"(c)); return d;
}
static __device__ __forceinline__ u64 fadd2(u64 a, u64 b){
    u64 d; asm("add.rn.f32x2 %0, %1, %2;" : "=l"(d) : "l"(a), "l"(b)); return d;
}
static __device__ __forceinline__ u64 pack2(float x){
    u64 r; asm("mov.b64 %0, {%1, %1};" : "=l"(r) : "f"(x)); return r;
}
static __device__ __forceinline__ u64 pack2b(float x, float y){
    u64 r; asm("mov.b64 %0, {%1, %2};" : "=l"(r) : "f"(x), "f"(y)); return r;
}
static __device__ __forceinline__ float2 unpack2(u64 v){
    float lo, hi; asm("mov.b64 {%0, %1}, %2;" : "=f"(lo), "=f"(hi) : "l"(v)); return make_float2(lo, hi);
}
static __device__ __forceinline__ u32 smaddr(const void* p){
    u32 a; asm("{ .reg .u64 t; cvta.to.shared.u64 t, %1; cvt.u32.u64 %0, t; }" : "=r"(a) : "l"(p)); return a;
}
static __device__ __forceinline__ void cp16(u32 dst, const void* src){
    asm volatile("cp.async.cg.shared.global [%0], [%1], 16;" :: "r"(dst), "l"(src));
}
#define CP_COMMIT() asm volatile("cp.async.commit_group;" ::: "memory")
#define CP_WAIT0()  asm volatile("cp.async.wait_group 0;" ::: "memory")
#define CP_WAIT1()  asm volatile("cp.async.wait_group 1;" ::: "memory")

// ---------------- smem layout (float offsets) ----------------
#define SHR   0        // SOBS [36][132] / SH1 [64][132] / PF buffer = 8448
#define XSB   4752     // staging buffer B (2304 floats) in SHR rows 36-53 (dead until epilogue1)
#define WRG   8448     // W1 compact [36][64]=2304, then W2 [64][64]=4096 (overwrites)
#define XSA   10752    // staging buffer A: 16 batches * 144 floats = 2304
#define SB1   13056    // 64
#define SB2   13120    // 64
#define SWD   13184    // 64 float2 = 128
#define SCC   13312    // 2 (+2 pad)
#define SMEM_FLOATS 13316   // 53264 B -> 4 CTAs/SM

#define BPB   128
#define TILEB 128
#define LDA   132

// one k-step: 4 batches x 16 outputs per thread.
// A-load: 8-distinct x 4-dup float4 = 1 wavefront. W-loads: 4-distinct x 8-dup = 1 wf each.
#define K_STEP(AP, WP, KK) do { \
    ulonglong2 Av = *(const ulonglong2*)((AP) + (KK)*LDA); \
    float4 Wa = *(const float4*)((WP) + (KK)*64); \
    float4 Wb = *(const float4*)((WP) + (KK)*64 + 4); \
    float4 Wc = *(const float4*)((WP) + (KK)*64 + 8); \
    float4 Wd = *(const float4*)((WP) + (KK)*64 + 12); \
    u64 a0 = Av.x, a1 = Av.y; \
    u64 w; \
    w = pack2(Wa.x); acc[0]  = ffma2(a0,w,acc[0]);  acc[1]  = ffma2(a1,w,acc[1]); \
    w = pack2(Wa.y); acc[2]  = ffma2(a0,w,acc[2]);  acc[3]  = ffma2(a1,w,acc[3]); \
    w = pack2(Wa.z); acc[4]  = ffma2(a0,w,acc[4]);  acc[5]  = ffma2(a1,w,acc[5]); \
    w = pack2(Wa.w); acc[6]  = ffma2(a0,w,acc[6]);  acc[7]  = ffma2(a1,w,acc[7]); \
    w = pack2(Wb.x); acc[8]  = ffma2(a0,w,acc[8]);  acc[9]  = ffma2(a1,w,acc[9]); \
    w = pack2(Wb.y); acc[10] = ffma2(a0,w,acc[10]); acc[11] = ffma2(a1,w,acc[11]); \
    w = pack2(Wb.z); acc[12] = ffma2(a0,w,acc[12]); acc[13] = ffma2(a1,w,acc[13]); \
    w = pack2(Wb.w); acc[14] = ffma2(a0,w,acc[14]); acc[15] = ffma2(a1,w,acc[15]); \
    w = pack2(Wc.x); acc[16] = ffma2(a0,w,acc[16]); acc[17] = ffma2(a1,w,acc[17]); \
    w = pack2(Wc.y); acc[18] = ffma2(a0,w,acc[18]); acc[19] = ffma2(a1,w,acc[19]); \
    w = pack2(Wc.z); acc[20] = ffma2(a0,w,acc[20]); acc[21] = ffma2(a1,w,acc[21]); \
    w = pack2(Wc.w); acc[22] = ffma2(a0,w,acc[22]); acc[23] = ffma2(a1,w,acc[23]); \
    w = pack2(Wd.x); acc[24] = ffma2(a0,w,acc[24]); acc[25] = ffma2(a1,w,acc[25]); \
    w = pack2(Wd.y); acc[26] = ffma2(a0,w,acc[26]); acc[27] = ffma2(a1,w,acc[27]); \
    w = pack2(Wd.z); acc[28] = ffma2(a0,w,acc[28]); acc[29] = ffma2(a1,w,acc[29]); \
    w = pack2(Wd.w); acc[30] = ffma2(a0,w,acc[30]); acc[31] = ffma2(a1,w,acc[31]); \
} while(0)

// issue one 16-batch staging wave into buffer BUF (float offset)
#define ISSUE_WAVE(WV, BUF) do { \
    long gb = ((long)(b0 + (WV)*16 + slb)) * 35; \
    u32 db = smb + (u32)(((BUF) + slb*144) * 4); \
    _Pragma("unroll") \
    for (int j = 0; j < 5; j++){ \
        int f4 = sq + 8*j; \
        if (f4 < 35){ \
            long gi = gb + f4; \
            if (gi < nf4) cp16(db + (u32)(f4*16), (const float4*)x + gi); \
        } \
    } \
    CP_COMMIT(); \
} while(0)

__global__ __launch_bounds__(BPB, 4) void maddpg_v11_kernel(
    const float* __restrict__ x,
    const float* __restrict__ W1, const float* __restrict__ b1,
    const float* __restrict__ W2, const float* __restrict__ b2,
    const float* __restrict__ W3, const float* __restrict__ b3,
    const int* __restrict__ idx,
    float* __restrict__ out, int B)
{
    extern __shared__ float sm[];
    __shared__ int sIdx[8];
    __shared__ int sActive[5];
    const int tid  = threadIdx.x;
    const int wid  = tid >> 5;
    const int lane = tid & 31;
    const int bq   = lane & 7;     // batch quad within warp's 32-batch slice
    const int og   = lane >> 3;    // output group (16 outputs at 16*og)
    const u32 smb = smaddr(sm);
    const int b0  = blockIdx.x * TILEB;
    const long nf4 = (long)B * 35;

    // staging map: warp covers 4 batches of the 16-batch wave
    const int slb = 4*wid + (lane >> 3);
    const int sq  = lane & 7;

    // ---- prologue: wave 0 into A, weights, wave 1 into B ----
    ISSUE_WAVE(0, XSA);
    if (tid < 8)  sIdx[tid] = idx[tid];
    if (tid < 5)  sActive[tid] = 0;
    // W1 compacted to 36 rows (structurally-zero obs rows dropped)
    #pragma unroll
    for (int j = 0; j < 5; j++){
        int i = j*BPB + tid;
        if (i < 576){
            int ck = i >> 4, nq = i & 15;
            int o;
            if (ck < 5)       o = ck;
            else if (ck < 11) { int m = (ck-5) >> 1; o = 5 + 3*m + ((ck-5)&1); }
            else              o = 14 + (ck - 11);
            ((float4*)(sm + WRG))[i] = ((const float4*)W1)[o*16 + nq];
        }
    }
    if (tid < 16) ((float4*)(sm + SB1))[tid] = ((const float4*)b1)[tid];
    else if (tid < 32) ((float4*)(sm + SB2))[tid-16] = ((const float4*)b2)[tid-16];
    if (tid < 64){
        float a1 = W3[tid*5+1], a2 = W3[tid*5+2], a3 = W3[tid*5+3], a4 = W3[tid*5+4];
        ((float2*)(sm + SWD))[tid] = make_float2(a1 - a2, a3 - a4);
    }
    if (tid == 0) *(float2*)(sm + SCC) = make_float2(b3[1]-b3[2], b3[3]-b3[4]);
    ISSUE_WAVE(1, XSB);

    // obs-build role map: warp-uniform, half-warp sub-roles
    const int half = lane >> 4;
    const int olb  = lane & 15;

    // ---- 8 pipelined staging waves ----
    #pragma unroll 1
    for (int w = 0; w < 8; w++){
        if (w == 7) { CP_WAIT0(); } else { CP_WAIT1(); }
        __syncthreads();
        {
            const int xbuf = (w & 1) ? XSB : XSA;
            const float* xb = sm + xbuf + olb*144;
            const float p0 = xb[0], p1 = xb[1];
            float* ob = sm + SHR + (w*16 + olb);
            if (wid == 0){
                if (half == 0){
                    ob[0*LDA] = p0;    ob[1*LDA] = p1;    ob[2*LDA] = xb[2];
                    ob[3*LDA] = xb[3]; ob[4*LDA] = xb[4];
                } else {
                    const float* r = xb + (sIdx[7] + 10)*7;   // obstacle 4
                    float dx = r[0]-p0, dy = r[1]-p1;
                    bool in = (dx*dx + dy*dy) < 0.0225f;
                    if (in) sActive[4] = 1;
                    ob[31*LDA] = in ? dx   : 0.0f;
                    ob[32*LDA] = in ? dy   : 0.0f;
                    ob[33*LDA] = in ? r[2] : 0.0f;
                    ob[34*LDA] = in ? r[3] : 0.0f;
                    ob[35*LDA] = in ? r[4] : 0.0f;
                }
            } else if (wid == 1){
                if (half == 0){
                    #pragma unroll
                    for (int m = 0; m < 2; m++){
                        const float* r = xb + sIdx[m]*7;
                        ob[(5+2*m)*LDA] = (r[5] + r[0]) - p0;
                        ob[(6+2*m)*LDA] = (r[6] + r[1]) - p1;
                    }
                } else {
                    const float* r = xb + sIdx[2]*7;
                    ob[9*LDA]  = (r[5] + r[0]) - p0;
                    ob[10*LDA] = (r[6] + r[1]) - p1;
                }
            } else {
                int m = (wid - 2)*2 + half;                   // obstacles 0..3
                const float* r = xb + (sIdx[3+m] + 10)*7;
                float dx = r[0]-p0, dy = r[1]-p1;
                bool in = (dx*dx + dy*dy) < 0.0225f;
                if (in) sActive[m] = 1;
                int kb = 11 + 5*m;
                ob[(kb+0)*LDA] = in ? dx   : 0.0f;
                ob[(kb+1)*LDA] = in ? dy   : 0.0f;
                ob[(kb+2)*LDA] = in ? r[2] : 0.0f;
                ob[(kb+3)*LDA] = in ? r[3] : 0.0f;
                ob[(kb+4)*LDA] = in ? r[4] : 0.0f;
            }
        }
        __syncthreads();     // buffer consumed; safe to refill
        if (w < 6) ISSUE_WAVE(w+2, (w & 1) ? XSB : XSA);
    }

    int act0 = sActive[0], act1 = sActive[1], act2 = sActive[2],
        act3 = sActive[3], act4 = sActive[4];

    // ---- GEMM1: [128 x 36] * [36 x 64] ----
    u64 acc[32];
    #pragma unroll
    for (int i = 0; i < 32; i++) acc[i] = 0ull;
    {
        const float* ap = sm + SHR + 32*wid + 4*bq;
        const float* wp = sm + WRG + 16*og;
        #pragma unroll
        for (int k = 0; k < 11; k++) K_STEP(ap, wp, k);
        if (act0){
            #pragma unroll
            for (int k = 11; k < 16; k++) K_STEP(ap, wp, k);
        }
        if (act1){
            #pragma unroll
            for (int k = 16; k < 21; k++) K_STEP(ap, wp, k);
        }
        if (act2){
            #pragma unroll
            for (int k = 21; k < 26; k++) K_STEP(ap, wp, k);
        }
        if (act3){
            #pragma unroll
            for (int k = 26; k < 31; k++) K_STEP(ap, wp, k);
        }
        if (act4){
            #pragma unroll
            for (int k = 31; k < 36; k++) K_STEP(ap, wp, k);
        }
    }
    __syncthreads();     // all W1 + SOBS reads complete

    // ---- issue W2 load over the W1/XSA region ----
    #pragma unroll
    for (int j = 0; j < 8; j++)
        cp16(smb + (u32)((WRG + (j*BPB + tid)*4) * 4), (const float4*)W2 + j*BPB + tid);
    CP_COMMIT();

    // ---- epilogue 1: relu(acc + b1) -> SH1 rows ----
    #pragma unroll
    for (int o = 0; o < 16; o++){
        float bv = sm[SB1 + 16*og + o];
        float2 f0 = unpack2(acc[2*o]);
        float2 f1 = unpack2(acc[2*o+1]);
        float4 v;
        v.x = fmaxf(f0.x + bv, 0.0f); v.y = fmaxf(f0.y + bv, 0.0f);
        v.z = fmaxf(f1.x + bv, 0.0f); v.w = fmaxf(f1.y + bv, 0.0f);
        *(float4*)(sm + SHR + (16*og + o)*LDA + 32*wid + 4*bq) = v;
    }
    CP_WAIT0();
    __syncthreads();     // SH1 visible + W2 landed

    // ---- GEMM2: [128 x 64] * [64 x 64] ----
    #pragma unroll
    for (int i = 0; i < 32; i++) acc[i] = 0ull;
    {
        const float* ap = sm + SHR + 32*wid + 4*bq;
        const float* wp = sm + WRG + 16*og;
        #pragma unroll 8
        for (int k = 0; k < 64; k++) K_STEP(ap, wp, k);
    }
    __syncthreads();     // SH1 reads done; SHR free for PF buffer

    // ---- register fold over this thread's 16 outputs ----
    {
        u64 pfx[2], pfy[2];
        pfx[0] = pfx[1] = pfy[0] = pfy[1] = 0ull;
        #pragma unroll
        for (int o = 0; o < 16; o++){
            float bv = sm[SB2 + 16*og + o];
            float2 wdv = ((const float2*)(sm + SWD))[16*og + o];
            u64 wx = pack2(wdv.x), wy = pack2(wdv.y);
            #pragma unroll
            for (int h = 0; h < 2; h++){
                float2 f = unpack2(acc[2*o + h]);
                u64 rr = pack2b(fmaxf(f.x + bv, 0.0f), fmaxf(f.y + bv, 0.0f));
                pfx[h] = ffma2(rr, wx, pfx[h]);
                pfy[h] = ffma2(rr, wy, pfy[h]);
            }
        }
        // partials: pf[og][batch_pair], batch_pair = 16*wid + 2*bq + h
        ulonglong2* pf = (ulonglong2*)(sm + SHR);
        #pragma unroll
        for (int h = 0; h < 2; h++){
            ulonglong2 v; v.x = pfx[h]; v.y = pfy[h];
            pf[og*64 + 16*wid + 2*bq + h] = v;
        }
    }
    __syncthreads();

    // ---- reduce over 4 output-groups, scale, clip, store ----
    if (tid < 64){
        const ulonglong2* pf = (const ulonglong2*)(sm + SHR);
        float2 cc = *(const float2*)(sm + SCC);
        u64 ax = pack2(cc.x), ay = pack2(cc.y);
        #pragma unroll
        for (int t = 0; t < 4; t++){
            ulonglong2 v = pf[t*64 + tid];
            ax = fadd2(ax, v.x);
            ay = fadd2(ay, v.y);
        }
        float2 rx = unpack2(ax);
        float2 ry = unpack2(ay);
        float v0 = rx.x * 0.1f, v1 = ry.x * 0.1f;
        float v2 = rx.y * 0.1f, v3 = ry.y * 0.1f;
        if (fabsf(v0) > 1.0f) v0 = copysignf(2.0f, v0);
        if (fabsf(v1) > 1.0f) v1 = copysignf(2.0f, v1);
        if (fabsf(v2) > 1.0f) v2 = copysignf(2.0f, v2);
        if (fabsf(v3) > 1.0f) v3 = copysignf(2.0f, v3);
        int b = b0 + 2*tid;
        if (b < B){
            float4 o4; o4.x = v0; o4.y = v1; o4.z = v2; o4.w = v3;
            ((float4*)out)[(b0 >> 1) + tid] = o4;
        }
    }
}

extern "C" void kernel_launch(void* const* d_in, const int* in_sizes, int n_in,
                              void* d_out, int out_size)
{
    const float* x  = (const float*)d_in[0];
    const float* W1 = (const float*)d_in[1];
    const float* b1 = (const float*)d_in[2];
    const float* W2 = (const float*)d_in[3];
    const float* b2 = (const float*)d_in[4];
    const float* W3 = (const float*)d_in[5];
    const float* b3 = (const float*)d_in[6];
    const int*  idx = (const int*)d_in[7];

    const int B = in_sizes[0] / 140;
    const int blocks = (B + TILEB - 1) / TILEB;
    const size_t smem = SMEM_FLOATS * sizeof(float);

    cudaFuncSetAttribute(maddpg_v11_kernel,
                         cudaFuncAttributeMaxDynamicSharedMemorySize, (int)smem);

    maddpg_v11_kernel<<<blocks, BPB, smem>>>(x, W1, b1, W2, b2, W3, b3, idx,
                                             (float*)d_out, B);
}